// round 13
// baseline (speedup 1.0000x reference)
#include <cuda_runtime.h>
#include <cuda_fp16.h>
#include <math.h>

#define BB 8
#define SS 512
#define HH 256
#define AA 64
#define ROWS (BB*SS)   // 4096
#define TI 8           // i-rows per attn block
#define NPROJ 128      // proj blocks: 32 rows x 128 cols each (16 per batch)
#define NATTN 512      // attn blocks: 64 per batch

// Scratch (allocation-free rule: __device__ globals)
__device__ float        g_ta[ROWS * AA];         // [row][a], bias folded in (f32)
__device__ unsigned int g_jaT16[(AA/2) * ROWS];  // [a-pair][row], half2
__device__ int          g_flag[BB];              // proj completion counters

namespace rk {

union F2 { unsigned long long u; float2 f; };

__device__ __forceinline__ unsigned long long fma2(
    unsigned long long a, unsigned long long b, unsigned long long c) {
    unsigned long long d;
    asm("fma.rn.f32x2 %0, %1, %2, %3;" : "=l"(d) : "l"(a), "l"(b), "l"(c));
    return d;
}

__device__ __forceinline__ __half2 rk_tanh_f16x2(__half2 x) {
    unsigned int xi = *reinterpret_cast<unsigned int*>(&x);
    unsigned int yi;
    asm("tanh.approx.f16x2 %0, %1;" : "=r"(yi) : "r"(xi));
    return *reinterpret_cast<__half2*>(&yi);
}

// mixed-precision FMA: f16 x f16 + f32 -> f32 (fma pipe, no XU)
__device__ __forceinline__ float fmah(unsigned short a, unsigned short b, float c) {
    float d;
    asm("fma.rn.f32.f16 %0, %1, %2, %3;" : "=f"(d) : "h"(a), "h"(b), "f"(c));
    return d;
}

__device__ __forceinline__ int ld_vol(const int* p) {
    return *reinterpret_cast<const volatile int*>(p);
}

} // namespace rk

using rk::F2;
using rk::fma2;
using rk::rk_tanh_f16x2;
using rk::fmah;
using rk::ld_vol;

// ---------------------------------------------------------------------------
// Kernel 0: reset flags (graph replays reuse device state).
// ---------------------------------------------------------------------------
__global__ void zero_flags_kernel() {
    if (threadIdx.x < BB) g_flag[threadIdx.x] = 0;
}

// ---------------------------------------------------------------------------
// Fused kernel: 640 blocks x 512 threads, 4 blocks/SM (592 slots).
//   bid 0..127   : proj  (row0 = bid*32; batch = bid>>4)
//                  THIN micro-tile: lane = row, warp = 8 cols -> acc[4] F2
//                  only (~26 regs, no spill under the 32-reg budget).
//   bid 128..639 : attn  (idx = bid-128, batch = idx>>6, i0 = (idx&63)*TI)
// Wave 1 = all proj + 464 attn; last 48 attn backfill as proj retires (~5us).
// ---------------------------------------------------------------------------
__global__ void __launch_bounds__(512, 4) fused_kernel(
    const float* __restrict__ x,
    const float* __restrict__ w_ta,
    const float* __restrict__ w_ja,
    const float* __restrict__ bias,
    const float* __restrict__ v,
    float* __restrict__ out)
{
    const int bid = blockIdx.x;
    const int tid = threadIdx.x;

    if (bid < NPROJ) {
        // ============================ PROJ ============================
        __shared__ float Xs[64 * 32];     // [kk][row^swz]   8KB
        __shared__ float Ws[64 * 128];    // [kk][a2^swz]   32KB

        const int b    = bid >> 4;        // batch (16 proj blocks each)
        const int row0 = bid * 32;
        const int lane = tid & 31;        // row within tile
        const int wp   = tid >> 5;        // warp 0..15 -> cols wp*8..wp*8+7

        F2 acc[4];                        // 4 col-pairs for 8 cols
#pragma unroll
        for (int i = 0; i < 4; ++i) acc[i].u = 0ull;

        for (int kc = 0; kc < HH; kc += 64) {
            // X chunk: 32 rows x 64 k = 512 float4, exactly 1 per thread
            {
                int r = tid >> 4, q = tid & 15;
                float4 f = *reinterpret_cast<const float4*>(
                    x + (size_t)(row0 + r) * HH + kc + q * 4);
                int c = r ^ ((q & 7) << 2);
                Xs[(q * 4 + 0) * 32 + c] = f.x;
                Xs[(q * 4 + 1) * 32 + c] = f.y;
                Xs[(q * 4 + 2) * 32 + c] = f.z;
                Xs[(q * 4 + 3) * 32 + c] = f.w;
            }
            // W chunk: 128 a2-rows x 64 k = 2048 float4, 4 per thread
#pragma unroll
            for (int m = 0; m < 4; ++m) {
                int idx = tid + m * 512;
                int cr = idx >> 4, q = idx & 15;
                const float* wsrc = (cr < 64) ? (w_ta + (size_t)cr * HH)
                                              : (w_ja + (size_t)(cr - 64) * HH);
                float4 f = *reinterpret_cast<const float4*>(wsrc + kc + q * 4);
                int c = cr ^ ((q & 7) << 2);
                Ws[(q * 4 + 0) * 128 + c] = f.x;
                Ws[(q * 4 + 1) * 128 + c] = f.y;
                Ws[(q * 4 + 2) * 128 + c] = f.z;
                Ws[(q * 4 + 3) * 128 + c] = f.w;
            }
            __syncthreads();

#pragma unroll 8
            for (int kk = 0; kk < 64; ++kk) {
                const int swz = ((kk >> 2) & 7) << 2;
                float xv = Xs[kk * 32 + (lane ^ swz)];            // conflict-free
                ulonglong2 w01 = *reinterpret_cast<const ulonglong2*>(
                    &Ws[kk * 128 + ((wp * 8) ^ swz)]);            // broadcast
                ulonglong2 w23 = *reinterpret_cast<const ulonglong2*>(
                    &Ws[kk * 128 + ((wp * 8 + 4) ^ swz)]);        // broadcast
                F2 xd; xd.f = make_float2(xv, xv);
                acc[0].u = fma2(xd.u, w01.x, acc[0].u);
                acc[1].u = fma2(xd.u, w01.y, acc[1].u);
                acc[2].u = fma2(xd.u, w23.x, acc[2].u);
                acc[3].u = fma2(xd.u, w23.y, acc[3].u);
            }
            __syncthreads();
        }

        const int row = row0 + lane;
        const int c0  = wp * 8;
        if (c0 < 64) {
            // ta: add bias, two float4 stores [row][a]
            float4 b0 = *reinterpret_cast<const float4*>(bias + c0);
            float4 b1 = *reinterpret_cast<const float4*>(bias + c0 + 4);
            float4 o0, o1;
            o0.x = acc[0].f.x + b0.x;  o0.y = acc[0].f.y + b0.y;
            o0.z = acc[1].f.x + b0.z;  o0.w = acc[1].f.y + b0.w;
            o1.x = acc[2].f.x + b1.x;  o1.y = acc[2].f.y + b1.y;
            o1.z = acc[3].f.x + b1.z;  o1.w = acc[3].f.y + b1.w;
            *reinterpret_cast<float4*>(&g_ta[(size_t)row * AA + c0])     = o0;
            *reinterpret_cast<float4*>(&g_ta[(size_t)row * AA + c0 + 4]) = o1;
        } else {
            // ja: 4 a-pairs; scalar stores, lanes = consecutive rows (coalesced)
            const int ap0 = (c0 - 64) >> 1;
#pragma unroll
            for (int t = 0; t < 4; ++t) {
                __half2 h = __floats2half2_rn(acc[t].f.x, acc[t].f.y);
                g_jaT16[(size_t)(ap0 + t) * ROWS + row] =
                    *reinterpret_cast<unsigned int*>(&h);
            }
        }

        __threadfence();
        __syncthreads();
        if (tid == 0) atomicAdd(&g_flag[b], 1);
        return;
    }

    // ============================ ATTN ============================
    __shared__ __half2 ta16[AA][4];     // [a][i-pair p]
    __shared__ unsigned int v16p[AA/2];
    __shared__ float redm[TI][16];
    __shared__ float reds[TI][16];
    __shared__ float gmaxs[TI];
    __shared__ float sums[TI];

    const int idx = bid - NPROJ;
    const int b   = idx >> 6;
    const int i0  = (idx & 63) * TI;
    const int j   = tid;
    const int lane = j & 31;
    const int warp = j >> 5;

    // wait for this batch's 16 proj blocks
    if (tid == 0) {
        while (ld_vol(&g_flag[b]) < 16) __nanosleep(200);
    }
    __syncthreads();

    // setup: pack ta into f16x2 i-pairs; pack v
    if (j < 256) {
        int a = j >> 2, p = j & 3;
        float lo = __ldcg(&g_ta[(size_t)(b * SS + i0 + 2 * p)     * AA + a]);
        float hi = __ldcg(&g_ta[(size_t)(b * SS + i0 + 2 * p + 1) * AA + a]);
        ta16[a][p] = __floats2half2_rn(lo, hi);
    } else if (j < 256 + AA / 2) {
        int ap = j - 256;
        __half2 h = __floats2half2_rn(v[2 * ap], v[2 * ap + 1]);
        v16p[ap] = *reinterpret_cast<unsigned int*>(&h);
    }
    __syncthreads();

    float acc[TI];
#pragma unroll
    for (int i = 0; i < TI; ++i) acc[i] = 0.f;

    const unsigned int* jp = g_jaT16 + b * SS + j;
#pragma unroll 4
    for (int ap = 0; ap < AA / 2; ++ap) {
        unsigned int jraw = __ldcg(&jp[(size_t)ap * ROWS]);
        __half2 jv  = *reinterpret_cast<__half2*>(&jraw);
        __half2 jv0 = __low2half2(jv);
        __half2 jv1 = __high2half2(jv);
        unsigned int vp = v16p[ap];
        unsigned short vh0 = (unsigned short)(vp & 0xffffu);
        unsigned short vh1 = (unsigned short)(vp >> 16);
        uint4 ra0 = *reinterpret_cast<const uint4*>(&ta16[2 * ap][0]);
        uint4 ra1 = *reinterpret_cast<const uint4*>(&ta16[2 * ap + 1][0]);
        const unsigned int* pa0 = reinterpret_cast<const unsigned int*>(&ra0);
        const unsigned int* pa1 = reinterpret_cast<const unsigned int*>(&ra1);
#pragma unroll
        for (int p = 0; p < 4; ++p) {
            __half2 t0 = rk_tanh_f16x2(__hadd2(*reinterpret_cast<const __half2*>(&pa0[p]), jv0));
            __half2 t1 = rk_tanh_f16x2(__hadd2(*reinterpret_cast<const __half2*>(&pa1[p]), jv1));
            unsigned int u0 = *reinterpret_cast<unsigned int*>(&t0);
            unsigned int u1 = *reinterpret_cast<unsigned int*>(&t1);
            acc[2 * p]     = fmah((unsigned short)(u0 & 0xffffu), vh0, acc[2 * p]);
            acc[2 * p]     = fmah((unsigned short)(u1 & 0xffffu), vh1, acc[2 * p]);
            acc[2 * p + 1] = fmah((unsigned short)(u0 >> 16),     vh0, acc[2 * p + 1]);
            acc[2 * p + 1] = fmah((unsigned short)(u1 >> 16),     vh1, acc[2 * p + 1]);
        }
    }

    // ---- block max per row ----
#pragma unroll
    for (int i = 0; i < TI; ++i) {
        float mx = acc[i];
#pragma unroll
        for (int o = 16; o; o >>= 1) mx = fmaxf(mx, __shfl_xor_sync(0xffffffffu, mx, o));
        if (lane == 0) redm[i][warp] = mx;
    }
    __syncthreads();
    if (warp < TI) {
        float m = (lane < 16) ? redm[warp][lane] : -INFINITY;
#pragma unroll
        for (int o = 8; o; o >>= 1) m = fmaxf(m, __shfl_xor_sync(0xffffffffu, m, o));
        if (lane == 0) gmaxs[warp] = m;
    }
    __syncthreads();

    // ---- exp + block sum per row ----
    float e[TI];
#pragma unroll
    for (int i = 0; i < TI; ++i) {
        e[i] = __expf(acc[i] - gmaxs[i]);
        float sm = e[i];
#pragma unroll
        for (int o = 16; o; o >>= 1) sm += __shfl_xor_sync(0xffffffffu, sm, o);
        if (lane == 0) reds[i][warp] = sm;
    }
    __syncthreads();
    if (warp < TI) {
        float t = (lane < 16) ? reds[warp][lane] : 0.f;
#pragma unroll
        for (int o = 8; o; o >>= 1) t += __shfl_xor_sync(0xffffffffu, t, o);
        if (lane == 0) sums[warp] = t;
    }
    __syncthreads();

#pragma unroll
    for (int i = 0; i < TI; ++i) {
        float inv = __fdividef(1.f, sums[i]);
        out[(size_t)(b * SS + i0 + i) * SS + j] = e[i] * inv;
    }
}

// ---------------------------------------------------------------------------
extern "C" void kernel_launch(void* const* d_in, const int* in_sizes, int n_in,
                              void* d_out, int out_size)
{
    const float* x    = (const float*)d_in[0];  // relation_hidden (B,S,H)
    const float* wta  = (const float*)d_in[1];  // (A,H)
    const float* wja  = (const float*)d_in[2];  // (A,H)
    const float* bias = (const float*)d_in[3];  // (1,1,1,A)
    const float* v    = (const float*)d_in[4];  // (1,A)

    zero_flags_kernel<<<1, 32>>>();
    fused_kernel<<<NPROJ + NATTN, 512>>>(x, wta, wja, bias, v, (float*)d_out);
}

// round 14
// speedup vs baseline: 1.2912x; 1.2912x over previous
#include <cuda_runtime.h>
#include <cuda_fp16.h>
#include <math.h>

#define BB 8
#define SS 512
#define HH 256
#define AA 64
#define ROWS (BB*SS)   // 4096
#define TI 4           // i-rows per attn block (fine granularity)

// Scratch (allocation-free rule: __device__ globals)
__device__ float        g_ta[ROWS * AA];         // [row][a], bias folded in (f32)
__device__ unsigned int g_jaT16[(AA/2) * ROWS];  // [a-pair][row], half2

namespace rk {

union F2 { unsigned long long u; float2 f; };

__device__ __forceinline__ unsigned long long fma2(
    unsigned long long a, unsigned long long b, unsigned long long c) {
    unsigned long long d;
    asm("fma.rn.f32x2 %0, %1, %2, %3;" : "=l"(d) : "l"(a), "l"(b), "l"(c));
    return d;
}

__device__ __forceinline__ __half2 rk_tanh_f16x2(__half2 x) {
    unsigned int xi = *reinterpret_cast<unsigned int*>(&x);
    unsigned int yi;
    asm("tanh.approx.f16x2 %0, %1;" : "=r"(yi) : "r"(xi));
    return *reinterpret_cast<__half2*>(&yi);
}

// mixed-precision FMA: f16 x f16 + f32 -> f32 (fma pipe, no XU)
__device__ __forceinline__ float fmah(unsigned short a, unsigned short b, float c) {
    float d;
    asm("fma.rn.f32.f16 %0, %1, %2, %3;" : "=f"(d) : "h"(a), "h"(b), "f"(c));
    return d;
}

} // namespace rk

using rk::F2;
using rk::fma2;
using rk::rk_tanh_f16x2;
using rk::fmah;

// ---------------------------------------------------------------------------
// Kernel 1: proj GEMM (R12 version, unchanged). 128 blocks x 128 threads.
// Block: 32 rows x 128 cols; micro-tile 8 rows x 4 cols; XOR-swizzled smem.
// ---------------------------------------------------------------------------
__global__ void __launch_bounds__(128) proj_gemm_kernel(
    const float* __restrict__ x,
    const float* __restrict__ w_ta,
    const float* __restrict__ w_ja,
    const float* __restrict__ bias)
{
    __shared__ float Xs[64 * 32];     // [kk][r^swz]   8KB
    __shared__ float Ws[64 * 128];    // [kk][a2^swz] 32KB

    const int tid  = threadIdx.x;
    const int rt   = tid >> 5;        // 0..3  -> rows rt*8..rt*8+7
    const int ct   = tid & 31;        // 0..31 -> cols ct*4..ct*4+3
    const int row0 = blockIdx.x * 32;

    F2 acc[8][2];
#pragma unroll
    for (int i = 0; i < 8; ++i) { acc[i][0].u = 0ull; acc[i][1].u = 0ull; }

    for (int kc = 0; kc < HH; kc += 64) {
#pragma unroll
        for (int m = 0; m < 4; ++m) {
            int idx = tid + m * 128;
            int r = idx >> 4, q = idx & 15;
            float4 f = *reinterpret_cast<const float4*>(
                x + (size_t)(row0 + r) * HH + kc + q * 4);
            int c = r ^ ((q & 7) << 2);
            Xs[(q * 4 + 0) * 32 + c] = f.x;
            Xs[(q * 4 + 1) * 32 + c] = f.y;
            Xs[(q * 4 + 2) * 32 + c] = f.z;
            Xs[(q * 4 + 3) * 32 + c] = f.w;
        }
#pragma unroll
        for (int m = 0; m < 16; ++m) {
            int idx = tid + m * 128;
            int cr = idx >> 4, q = idx & 15;
            const float* wsrc = (cr < 64) ? (w_ta + (size_t)cr * HH)
                                          : (w_ja + (size_t)(cr - 64) * HH);
            float4 f = *reinterpret_cast<const float4*>(wsrc + kc + q * 4);
            int c = cr ^ ((q & 7) << 2);
            Ws[(q * 4 + 0) * 128 + c] = f.x;
            Ws[(q * 4 + 1) * 128 + c] = f.y;
            Ws[(q * 4 + 2) * 128 + c] = f.z;
            Ws[(q * 4 + 3) * 128 + c] = f.w;
        }
        __syncthreads();

#pragma unroll 8
        for (int kk = 0; kk < 64; ++kk) {
            const int swz = ((kk >> 2) & 7) << 2;
            float4 xlo = *reinterpret_cast<const float4*>(&Xs[kk * 32 + ((rt * 8) ^ swz)]);
            float4 xhi = *reinterpret_cast<const float4*>(&Xs[kk * 32 + ((rt * 8 + 4) ^ swz)]);
            ulonglong2 wv = *reinterpret_cast<const ulonglong2*>(&Ws[kk * 128 + ((ct * 4) ^ swz)]);
            F2 xd;
            xd.f = make_float2(xlo.x, xlo.x);
            acc[0][0].u = fma2(xd.u, wv.x, acc[0][0].u);
            acc[0][1].u = fma2(xd.u, wv.y, acc[0][1].u);
            xd.f = make_float2(xlo.y, xlo.y);
            acc[1][0].u = fma2(xd.u, wv.x, acc[1][0].u);
            acc[1][1].u = fma2(xd.u, wv.y, acc[1][1].u);
            xd.f = make_float2(xlo.z, xlo.z);
            acc[2][0].u = fma2(xd.u, wv.x, acc[2][0].u);
            acc[2][1].u = fma2(xd.u, wv.y, acc[2][1].u);
            xd.f = make_float2(xlo.w, xlo.w);
            acc[3][0].u = fma2(xd.u, wv.x, acc[3][0].u);
            acc[3][1].u = fma2(xd.u, wv.y, acc[3][1].u);
            xd.f = make_float2(xhi.x, xhi.x);
            acc[4][0].u = fma2(xd.u, wv.x, acc[4][0].u);
            acc[4][1].u = fma2(xd.u, wv.y, acc[4][1].u);
            xd.f = make_float2(xhi.y, xhi.y);
            acc[5][0].u = fma2(xd.u, wv.x, acc[5][0].u);
            acc[5][1].u = fma2(xd.u, wv.y, acc[5][1].u);
            xd.f = make_float2(xhi.z, xhi.z);
            acc[6][0].u = fma2(xd.u, wv.x, acc[6][0].u);
            acc[6][1].u = fma2(xd.u, wv.y, acc[6][1].u);
            xd.f = make_float2(xhi.w, xhi.w);
            acc[7][0].u = fma2(xd.u, wv.x, acc[7][0].u);
            acc[7][1].u = fma2(xd.u, wv.y, acc[7][1].u);
        }
        __syncthreads();
    }

    const int c0 = ct * 4;
    const int rowb = row0 + rt * 8;
    if (c0 < 64) {
        float4 bb = *reinterpret_cast<const float4*>(bias + c0);
#pragma unroll
        for (int i = 0; i < 8; ++i) {
            int row = rowb + i;
            float4 o;
            o.x = acc[i][0].f.x + bb.x;
            o.y = acc[i][0].f.y + bb.y;
            o.z = acc[i][1].f.x + bb.z;
            o.w = acc[i][1].f.y + bb.w;
            *reinterpret_cast<float4*>(&g_ta[(size_t)row * AA + c0]) = o;
        }
    } else {
        const int ap0 = (c0 - 64) >> 1;
        uint4 sA0, sA1, sB0, sB1;
        __half2 h;
        h = __floats2half2_rn(acc[0][0].f.x, acc[0][0].f.y); sA0.x = *reinterpret_cast<unsigned int*>(&h);
        h = __floats2half2_rn(acc[1][0].f.x, acc[1][0].f.y); sA0.y = *reinterpret_cast<unsigned int*>(&h);
        h = __floats2half2_rn(acc[2][0].f.x, acc[2][0].f.y); sA0.z = *reinterpret_cast<unsigned int*>(&h);
        h = __floats2half2_rn(acc[3][0].f.x, acc[3][0].f.y); sA0.w = *reinterpret_cast<unsigned int*>(&h);
        h = __floats2half2_rn(acc[4][0].f.x, acc[4][0].f.y); sA1.x = *reinterpret_cast<unsigned int*>(&h);
        h = __floats2half2_rn(acc[5][0].f.x, acc[5][0].f.y); sA1.y = *reinterpret_cast<unsigned int*>(&h);
        h = __floats2half2_rn(acc[6][0].f.x, acc[6][0].f.y); sA1.z = *reinterpret_cast<unsigned int*>(&h);
        h = __floats2half2_rn(acc[7][0].f.x, acc[7][0].f.y); sA1.w = *reinterpret_cast<unsigned int*>(&h);
        h = __floats2half2_rn(acc[0][1].f.x, acc[0][1].f.y); sB0.x = *reinterpret_cast<unsigned int*>(&h);
        h = __floats2half2_rn(acc[1][1].f.x, acc[1][1].f.y); sB0.y = *reinterpret_cast<unsigned int*>(&h);
        h = __floats2half2_rn(acc[2][1].f.x, acc[2][1].f.y); sB0.z = *reinterpret_cast<unsigned int*>(&h);
        h = __floats2half2_rn(acc[3][1].f.x, acc[3][1].f.y); sB0.w = *reinterpret_cast<unsigned int*>(&h);
        h = __floats2half2_rn(acc[4][1].f.x, acc[4][1].f.y); sB1.x = *reinterpret_cast<unsigned int*>(&h);
        h = __floats2half2_rn(acc[5][1].f.x, acc[5][1].f.y); sB1.y = *reinterpret_cast<unsigned int*>(&h);
        h = __floats2half2_rn(acc[6][1].f.x, acc[6][1].f.y); sB1.z = *reinterpret_cast<unsigned int*>(&h);
        h = __floats2half2_rn(acc[7][1].f.x, acc[7][1].f.y); sB1.w = *reinterpret_cast<unsigned int*>(&h);
        *reinterpret_cast<uint4*>(&g_jaT16[(size_t)ap0 * ROWS + rowb])           = sA0;
        *reinterpret_cast<uint4*>(&g_jaT16[(size_t)ap0 * ROWS + rowb + 4])       = sA1;
        *reinterpret_cast<uint4*>(&g_jaT16[(size_t)(ap0 + 1) * ROWS + rowb])     = sB0;
        *reinterpret_cast<uint4*>(&g_jaT16[(size_t)(ap0 + 1) * ROWS + rowb + 4]) = sB1;
    }
}

// ---------------------------------------------------------------------------
// Kernel 2: scores + softmax. TI=4, 256 threads, 1024 blocks (7 blocks/SM,
// ~1% load imbalance). Thread owns j = tid and j+256. Same f16x2-tanh +
// fma.rn.f32.f16 inner math as round 8.
// ---------------------------------------------------------------------------
__global__ void __launch_bounds__(256, 7) attn_kernel(
    const float* __restrict__ v,
    float* __restrict__ out)
{
    __shared__ __half2 ta16[AA][2];     // [a][i-pair p], p=0,1 -> rows i0..i0+3
    __shared__ unsigned int v16p[AA/2];
    __shared__ float redm[TI][8];
    __shared__ float reds[TI][8];
    __shared__ float gmaxs[TI];
    __shared__ float sums[TI];

    const int blk = blockIdx.x;           // 0..1023
    const int b   = blk >> 7;             // batch
    const int i0  = (blk & 127) * TI;     // first i-row
    const int tid = threadIdx.x;          // 0..255
    const int lane = tid & 31;
    const int warp = tid >> 5;            // 0..7

    // setup: pack ta into f16x2 i-pairs; pack v
    if (tid < 128) {
        int a = tid >> 1, p = tid & 1;
        float lo = g_ta[(size_t)(b * SS + i0 + 2 * p)     * AA + a];
        float hi = g_ta[(size_t)(b * SS + i0 + 2 * p + 1) * AA + a];
        ta16[a][p] = __floats2half2_rn(lo, hi);
    } else if (tid < 128 + AA / 2) {
        int ap = tid - 128;
        __half2 h = __floats2half2_rn(v[2 * ap], v[2 * ap + 1]);
        v16p[ap] = *reinterpret_cast<unsigned int*>(&h);
    }
    __syncthreads();

    float accA[TI], accB[TI];             // j = tid, j = tid+256
#pragma unroll
    for (int i = 0; i < TI; ++i) { accA[i] = 0.f; accB[i] = 0.f; }

    const unsigned int* jp = g_jaT16 + b * SS + tid;
#pragma unroll 4
    for (int ap = 0; ap < AA / 2; ++ap) {
        unsigned int jrawA = jp[(size_t)ap * ROWS];
        unsigned int jrawB = jp[(size_t)ap * ROWS + 256];
        __half2 jA  = *reinterpret_cast<__half2*>(&jrawA);
        __half2 jA0 = __low2half2(jA);
        __half2 jA1 = __high2half2(jA);
        __half2 jB  = *reinterpret_cast<__half2*>(&jrawB);
        __half2 jB0 = __low2half2(jB);
        __half2 jB1 = __high2half2(jB);
        unsigned int vp = v16p[ap];
        unsigned short vh0 = (unsigned short)(vp & 0xffffu);
        unsigned short vh1 = (unsigned short)(vp >> 16);
        uint2 ra0 = *reinterpret_cast<const uint2*>(&ta16[2 * ap][0]);
        uint2 ra1 = *reinterpret_cast<const uint2*>(&ta16[2 * ap + 1][0]);
        const unsigned int* pa0 = reinterpret_cast<const unsigned int*>(&ra0);
        const unsigned int* pa1 = reinterpret_cast<const unsigned int*>(&ra1);
#pragma unroll
        for (int p = 0; p < 2; ++p) {
            __half2 tap0 = *reinterpret_cast<const __half2*>(&pa0[p]);
            __half2 tap1 = *reinterpret_cast<const __half2*>(&pa1[p]);
            // j-group A
            {
                __half2 t0 = rk_tanh_f16x2(__hadd2(tap0, jA0));
                __half2 t1 = rk_tanh_f16x2(__hadd2(tap1, jA1));
                unsigned int u0 = *reinterpret_cast<unsigned int*>(&t0);
                unsigned int u1 = *reinterpret_cast<unsigned int*>(&t1);
                accA[2 * p]     = fmah((unsigned short)(u0 & 0xffffu), vh0, accA[2 * p]);
                accA[2 * p]     = fmah((unsigned short)(u1 & 0xffffu), vh1, accA[2 * p]);
                accA[2 * p + 1] = fmah((unsigned short)(u0 >> 16),     vh0, accA[2 * p + 1]);
                accA[2 * p + 1] = fmah((unsigned short)(u1 >> 16),     vh1, accA[2 * p + 1]);
            }
            // j-group B
            {
                __half2 t0 = rk_tanh_f16x2(__hadd2(tap0, jB0));
                __half2 t1 = rk_tanh_f16x2(__hadd2(tap1, jB1));
                unsigned int u0 = *reinterpret_cast<unsigned int*>(&t0);
                unsigned int u1 = *reinterpret_cast<unsigned int*>(&t1);
                accB[2 * p]     = fmah((unsigned short)(u0 & 0xffffu), vh0, accB[2 * p]);
                accB[2 * p]     = fmah((unsigned short)(u1 & 0xffffu), vh1, accB[2 * p]);
                accB[2 * p + 1] = fmah((unsigned short)(u0 >> 16),     vh0, accB[2 * p + 1]);
                accB[2 * p + 1] = fmah((unsigned short)(u1 >> 16),     vh1, accB[2 * p + 1]);
            }
        }
    }

    // ---- block max per row (over both j halves) ----
#pragma unroll
    for (int i = 0; i < TI; ++i) {
        float mx = fmaxf(accA[i], accB[i]);
#pragma unroll
        for (int o = 16; o; o >>= 1) mx = fmaxf(mx, __shfl_xor_sync(0xffffffffu, mx, o));
        if (lane == 0) redm[i][warp] = mx;
    }
    __syncthreads();
    if (warp < TI) {
        float m = (lane < 8) ? redm[warp][lane] : -INFINITY;
#pragma unroll
        for (int o = 4; o; o >>= 1) m = fmaxf(m, __shfl_xor_sync(0xffffffffu, m, o));
        if (lane == 0) gmaxs[warp] = m;
    }
    __syncthreads();

    // ---- exp + block sum per row ----
    float eA[TI], eB[TI];
#pragma unroll
    for (int i = 0; i < TI; ++i) {
        eA[i] = __expf(accA[i] - gmaxs[i]);
        eB[i] = __expf(accB[i] - gmaxs[i]);
        float sm = eA[i] + eB[i];
#pragma unroll
        for (int o = 16; o; o >>= 1) sm += __shfl_xor_sync(0xffffffffu, sm, o);
        if (lane == 0) reds[i][warp] = sm;
    }
    __syncthreads();
    if (warp < TI) {
        float t = (lane < 8) ? reds[warp][lane] : 0.f;
#pragma unroll
        for (int o = 4; o; o >>= 1) t += __shfl_xor_sync(0xffffffffu, t, o);
        if (lane == 0) sums[warp] = t;
    }
    __syncthreads();

#pragma unroll
    for (int i = 0; i < TI; ++i) {
        float inv = __fdividef(1.f, sums[i]);
        size_t rowoff = (size_t)(b * SS + i0 + i) * SS;
        out[rowoff + tid]       = eA[i] * inv;
        out[rowoff + tid + 256] = eB[i] * inv;
    }
}

// ---------------------------------------------------------------------------
extern "C" void kernel_launch(void* const* d_in, const int* in_sizes, int n_in,
                              void* d_out, int out_size)
{
    const float* x    = (const float*)d_in[0];  // relation_hidden (B,S,H)
    const float* wta  = (const float*)d_in[1];  // (A,H)
    const float* wja  = (const float*)d_in[2];  // (A,H)
    const float* bias = (const float*)d_in[3];  // (1,1,1,A)
    const float* v    = (const float*)d_in[4];  // (1,A)

    proj_gemm_kernel<<<ROWS / 32, 128>>>(x, wta, wja, bias);
    attn_kernel<<<(BB * SS / TI), 256>>>(v, (float*)d_out);
}